// round 8
// baseline (speedup 1.0000x reference)
#include <cuda_runtime.h>
#include <stdint.h>

// EmotionModel: out = r + clip(softmax(r * (e @ (W_Q^T W_K)))^3 * colsum(W_D) + sum(b_D), -1, 1)
// B = 1,048,576 rows, D = 7. HBM-bound: 84 MB traffic -> ~13 us floor.
// R8: byte-identical resubmission (broker infra failed pre-compile in R6/R7).
// Fix under test: 128-bit LDS/STS on under-aligned __shared__ float arrays
// caused R4/R5 "misaligned address"; staging buffers now __align__(16), first.

#define THREADS 256
#define RPT 2                              // rows per thread
#define ROWS_PER_BLOCK (THREADS * RPT)     // 512
#define D 7
#define FLOATS_PER_BLOCK (ROWS_PER_BLOCK * D)   // 3584
#define N4 (FLOATS_PER_BLOCK / 4)               // 896 float4s

template <bool VEC4>
__global__ __launch_bounds__(THREADS)
void emotion_kernel(const float* __restrict__ rep,
                    const float* __restrict__ emo,
                    const float* __restrict__ WQ,
                    const float* __restrict__ WK,
                    const float* __restrict__ WD,
                    const float* __restrict__ bD,
                    float* __restrict__ out)
{
    __shared__ __align__(16) float sE[FLOATS_PER_BLOCK];   // 14 KB staging (reused for output)
    __shared__ __align__(16) float sR[FLOATS_PER_BLOCK];   // 14 KB staging
    __shared__ float sWQ[49];
    __shared__ float sWK[49];
    __shared__ float sM[49];       // M[k][i] = sum_j WQ[j][k] * WK[j][i]
    __shared__ float sCol[D];      // colsum(W_D)
    __shared__ float sSumB;        // sum(b_D)

    const int tid = threadIdx.x;

    // ---- tiny per-block precompute -------------------------------------
    if (tid < 49) { sWQ[tid] = WQ[tid]; sWK[tid] = WK[tid]; }
    __syncthreads();
    if (tid < 49) {
        const int k = tid / 7, i = tid % 7;
        float acc = 0.f;
        #pragma unroll
        for (int j = 0; j < 7; j++) acc = fmaf(sWQ[j * 7 + k], sWK[j * 7 + i], acc);
        sM[tid] = acc;
    }
    if (tid >= 64 && tid < 64 + D) {
        const int i = tid - 64;
        float c = 0.f;
        #pragma unroll
        for (int j = 0; j < 7; j++) c += WD[j * 7 + i];
        sCol[i] = c;
    }
    if (tid == 96) {
        float s = 0.f;
        #pragma unroll
        for (int j = 0; j < 7; j++) s += bD[j];
        sSumB = s;
    }

    // ---- coalesced staging of both inputs ------------------------------
    const size_t base = (size_t)blockIdx.x * FLOATS_PER_BLOCK;   // 14336B per block
    if (VEC4) {
        const float4* __restrict__ e4 = (const float4*)(emo + base);
        const float4* __restrict__ r4 = (const float4*)(rep + base);
        float4* se4 = (float4*)sE;
        float4* sr4 = (float4*)sR;
        #pragma unroll
        for (int i = tid; i < N4; i += THREADS) {
            se4[i] = e4[i];
            sr4[i] = r4[i];
        }
    } else {
        // Scalar fallback: consecutive lanes read consecutive floats -> still
        // one 128B wavefront per warp-LDG; only instruction count rises.
        const float* __restrict__ ep = emo + base;
        const float* __restrict__ rp = rep + base;
        #pragma unroll 4
        for (int i = tid; i < FLOATS_PER_BLOCK; i += THREADS) {
            sE[i] = ep[i];
            sR[i] = rp[i];
        }
    }
    __syncthreads();   // covers sM/sCol/sSumB writes and staging stores

    const float col[D] = {sCol[0], sCol[1], sCol[2], sCol[3], sCol[4], sCol[5], sCol[6]};
    const float sumb = sSumB;

    // ---- per-row math (smem row access is bank-conflict-free: 7*tid mod 32) ----
    #pragma unroll
    for (int r = 0; r < RPT; r++) {
        const int row = tid + r * THREADS;
        float e[D], rv[D];
        #pragma unroll
        for (int i = 0; i < D; i++) { e[i] = sE[row * D + i]; rv[i] = sR[row * D + i]; }

        float raw[D];
        #pragma unroll
        for (int i = 0; i < D; i++) {
            float acc = 0.f;
            #pragma unroll
            for (int k = 0; k < D; k++) acc = fmaf(e[k], sM[k * 7 + i], acc);  // broadcast LDS
            raw[i] = acc * rv[i];
        }

        // softmax over 7
        float mx = raw[0];
        #pragma unroll
        for (int i = 1; i < D; i++) mx = fmaxf(mx, raw[i]);
        float p[D], psum = 0.f;
        #pragma unroll
        for (int i = 0; i < D; i++) { p[i] = __expf(raw[i] - mx); psum += p[i]; }
        const float inv = 1.0f / psum;

        #pragma unroll
        for (int i = 0; i < D; i++) {
            const float s  = p[i] * inv;
            const float s3 = s * s * s;
            const float d  = fminf(fmaxf(fmaf(s3, col[i], sumb), -1.0f), 1.0f);
            sE[row * D + i] = rv[i] + d;   // reuse e-staging buffer for output
        }
    }
    __syncthreads();

    // ---- coalesced store -----------------------------------------------
    if (VEC4) {
        float4* o4 = (float4*)(out + base);
        const float4* se4 = (const float4*)sE;
        #pragma unroll
        for (int i = tid; i < N4; i += THREADS) o4[i] = se4[i];
    } else {
        float* __restrict__ op = out + base;
        #pragma unroll 4
        for (int i = tid; i < FLOATS_PER_BLOCK; i += THREADS) op[i] = sE[i];
    }
}

extern "C" void kernel_launch(void* const* d_in, const int* in_sizes, int n_in,
                              void* d_out, int out_size)
{
    const float* rep = (const float*)d_in[0];
    const float* emo = (const float*)d_in[1];
    const float* WQ  = (const float*)d_in[2];
    const float* WK  = (const float*)d_in[3];
    const float* WD  = (const float*)d_in[4];
    const float* bD  = (const float*)d_in[5];
    float* out = (float*)d_out;

    const int n_rows = in_sizes[0] / D;                               // 1,048,576
    const int grid = (n_rows + ROWS_PER_BLOCK - 1) / ROWS_PER_BLOCK;  // 2048 exact

    const bool aligned16 =
        ((((uintptr_t)rep) | ((uintptr_t)emo) | ((uintptr_t)out)) & 15u) == 0;

    if (aligned16)
        emotion_kernel<true><<<grid, THREADS>>>(rep, emo, WQ, WK, WD, bD, out);
    else
        emotion_kernel<false><<<grid, THREADS>>>(rep, emo, WQ, WK, WD, bD, out);
}

// round 9
// speedup vs baseline: 1.1236x; 1.1236x over previous
#include <cuda_runtime.h>
#include <stdint.h>

// EmotionModel: out = r + clip(softmax(r * (e @ (W_Q^T W_K)))^3 * colsum(W_D) + sum(b_D), -1, 1)
// B = 1,048,576 rows, D = 7.
// R9: R8 measured 23.0us, DRAM 33%, L1 45%, occ 22.6% (regs=88 -> 2 CTAs/SM).
// Per-SM MUFU count (~49.6K) ~= measured cycles => XU pipe suspected saturated.
// Changes: (a) __expf -> FMA-pipe poly exp (2^f Taylor deg-5 + exponent bits),
//          (b) __launch_bounds__(256,4) to cap regs at 64 -> ~2x occupancy.

#define THREADS 256
#define RPT 2                              // rows per thread
#define ROWS_PER_BLOCK (THREADS * RPT)     // 512
#define D 7
#define FLOATS_PER_BLOCK (ROWS_PER_BLOCK * D)   // 3584
#define N4 (FLOATS_PER_BLOCK / 4)               // 896 float4s

// e^x on the FMA pipe (no MUFU). Valid for x in ~[-80, 0] (softmax: x <= 0).
// z = rn(x*log2e) captured via the 1.5*2^23 magic; f in [-0.5, 0.5];
// 2^f by degree-5 Taylor (rel err ~2.4e-6); scale by adding n<<23 to bits.
__device__ __forceinline__ float fexp(float x) {
    const float L2E = 1.442695041f;
    float z = fmaf(x, L2E, 12582912.0f);       // 1.5*2^23 magic round
    int   i = __float_as_int(z);               // low mantissa bits hold n (+bias)
    float n = z - 12582912.0f;
    float f = fmaf(x, L2E, -n);                // f in [-0.5, 0.5]
    float p =             1.3333558146e-3f;    // ln2^5/120
    p = fmaf(p, f,        9.6181291076e-3f);   // ln2^4/24
    p = fmaf(p, f,        5.5504108664e-2f);   // ln2^3/6
    p = fmaf(p, f,        2.4022650695e-1f);   // ln2^2/2
    p = fmaf(p, f,        6.9314718056e-1f);   // ln2
    p = fmaf(p, f,        1.0f);
    return __int_as_float(__float_as_int(p) + (i << 23));
}

template <bool VEC4>
__global__ __launch_bounds__(THREADS, 4)
void emotion_kernel(const float* __restrict__ rep,
                    const float* __restrict__ emo,
                    const float* __restrict__ WQ,
                    const float* __restrict__ WK,
                    const float* __restrict__ WD,
                    const float* __restrict__ bD,
                    float* __restrict__ out)
{
    __shared__ __align__(16) float sE[FLOATS_PER_BLOCK];   // 14 KB staging (reused for output)
    __shared__ __align__(16) float sR[FLOATS_PER_BLOCK];   // 14 KB staging
    __shared__ float sWQ[49];
    __shared__ float sWK[49];
    __shared__ float sM[49];       // M[k][i] = sum_j WQ[j][k] * WK[j][i]
    __shared__ float sCol[D];      // colsum(W_D)
    __shared__ float sSumB;        // sum(b_D)

    const int tid = threadIdx.x;

    // ---- tiny per-block precompute -------------------------------------
    if (tid < 49) { sWQ[tid] = WQ[tid]; sWK[tid] = WK[tid]; }
    __syncthreads();
    if (tid < 49) {
        const int k = tid / 7, i = tid % 7;
        float acc = 0.f;
        #pragma unroll
        for (int j = 0; j < 7; j++) acc = fmaf(sWQ[j * 7 + k], sWK[j * 7 + i], acc);
        sM[tid] = acc;
    }
    if (tid >= 64 && tid < 64 + D) {
        const int i = tid - 64;
        float c = 0.f;
        #pragma unroll
        for (int j = 0; j < 7; j++) c += WD[j * 7 + i];
        sCol[i] = c;
    }
    if (tid == 96) {
        float s = 0.f;
        #pragma unroll
        for (int j = 0; j < 7; j++) s += bD[j];
        sSumB = s;
    }

    // ---- coalesced staging of both inputs ------------------------------
    const size_t base = (size_t)blockIdx.x * FLOATS_PER_BLOCK;   // 14336B per block
    if (VEC4) {
        const float4* __restrict__ e4 = (const float4*)(emo + base);
        const float4* __restrict__ r4 = (const float4*)(rep + base);
        float4* se4 = (float4*)sE;
        float4* sr4 = (float4*)sR;
        #pragma unroll
        for (int i = tid; i < N4; i += THREADS) {
            se4[i] = e4[i];
            sr4[i] = r4[i];
        }
    } else {
        const float* __restrict__ ep = emo + base;
        const float* __restrict__ rp = rep + base;
        #pragma unroll 4
        for (int i = tid; i < FLOATS_PER_BLOCK; i += THREADS) {
            sE[i] = ep[i];
            sR[i] = rp[i];
        }
    }
    __syncthreads();   // covers sM/sCol/sSumB writes and staging stores

    const float col[D] = {sCol[0], sCol[1], sCol[2], sCol[3], sCol[4], sCol[5], sCol[6]};
    const float sumb = sSumB;

    // ---- per-row math (smem row access is bank-conflict-free: 7*tid mod 32) ----
    #pragma unroll
    for (int r = 0; r < RPT; r++) {
        const int row = tid + r * THREADS;
        float e[D], rv[D];
        #pragma unroll
        for (int i = 0; i < D; i++) { e[i] = sE[row * D + i]; rv[i] = sR[row * D + i]; }

        float raw[D];
        #pragma unroll
        for (int i = 0; i < D; i++) {
            float acc = 0.f;
            #pragma unroll
            for (int k = 0; k < D; k++) acc = fmaf(e[k], sM[k * 7 + i], acc);  // broadcast LDS
            raw[i] = acc * rv[i];
        }

        // softmax over 7 (exp on the FMA pipe, not MUFU)
        float mx = raw[0];
        #pragma unroll
        for (int i = 1; i < D; i++) mx = fmaxf(mx, raw[i]);
        float p[D], psum = 0.f;
        #pragma unroll
        for (int i = 0; i < D; i++) { p[i] = fexp(raw[i] - mx); psum += p[i]; }
        const float inv = __fdividef(1.0f, psum);

        #pragma unroll
        for (int i = 0; i < D; i++) {
            const float s  = p[i] * inv;
            const float s3 = s * s * s;
            const float d  = fminf(fmaxf(fmaf(s3, col[i], sumb), -1.0f), 1.0f);
            sE[row * D + i] = rv[i] + d;   // reuse e-staging buffer for output
        }
    }
    __syncthreads();

    // ---- coalesced store -----------------------------------------------
    if (VEC4) {
        float4* o4 = (float4*)(out + base);
        const float4* se4 = (const float4*)sE;
        #pragma unroll
        for (int i = tid; i < N4; i += THREADS) o4[i] = se4[i];
    } else {
        float* __restrict__ op = out + base;
        #pragma unroll 4
        for (int i = tid; i < FLOATS_PER_BLOCK; i += THREADS) op[i] = sE[i];
    }
}

extern "C" void kernel_launch(void* const* d_in, const int* in_sizes, int n_in,
                              void* d_out, int out_size)
{
    const float* rep = (const float*)d_in[0];
    const float* emo = (const float*)d_in[1];
    const float* WQ  = (const float*)d_in[2];
    const float* WK  = (const float*)d_in[3];
    const float* WD  = (const float*)d_in[4];
    const float* bD  = (const float*)d_in[5];
    float* out = (float*)d_out;

    const int n_rows = in_sizes[0] / D;                               // 1,048,576
    const int grid = (n_rows + ROWS_PER_BLOCK - 1) / ROWS_PER_BLOCK;  // 2048 exact

    const bool aligned16 =
        ((((uintptr_t)rep) | ((uintptr_t)emo) | ((uintptr_t)out)) & 15u) == 0;

    if (aligned16)
        emotion_kernel<true><<<grid, THREADS>>>(rep, emo, WQ, WK, WD, bD, out);
    else
        emotion_kernel<false><<<grid, THREADS>>>(rep, emo, WQ, WK, WD, bD, out);
}